// round 6
// baseline (speedup 1.0000x reference)
#include <cuda_runtime.h>

// ---------------------------------------------------------------------------
// GroupedQueryAttention:
//   x_embed affine in scalar x[b,s] => score(log2) = a[g,p]*x[b,s] + bconst[g,p,s]
//   attn = e/Z ; ctx = invZ*(sum_s e*vc[s,:] + (sum_s e*x)*vw) ; out = ctx@o_w+o_b
//
// k_main: grid (74,2) [g=blockIdx.y], 512 thr, 1 CTA/SM. Warp w owns pairs
// (2w, 2w+1) over full s; NB=2 batch rows per chunk (each bconst LDG.128 and
// vc LDS.128 serves 8 elements). Z for the next chunk's rows is computed in
// the same inner loop (reuses the bconst load). bconst LDGs use a 4-deep
// double-buffered prefetch ring. attn stores are streaming (__stcs).
// k_pre2: smem-staged, fully parallel table build (~3us).
// k_outproj: sync-free persistent GEMV epilogue (~4us).
// ---------------------------------------------------------------------------

#define LOG2E_OVER_SCALE ((float)(1.4426950408889634 / 2.8284271247461903))

// g_b4[g][wp][s2][4] = { b(2s2,p0), b(2s2,p1), b(2s2+1,p0), b(2s2+1,p1) }
__device__ __align__(16) float g_b4[2][16][512][4];   // 256 KB
// g_vc4[g][jj][s2][4] = { vc(2s2,2jj), vc(2s2,2jj+1), vc(2s2+1,2jj), vc(2s2+1,2jj+1) }
__device__ __align__(16) float g_vc4[2][4][512][4];   // 64 KB
__device__ float g_a[2][32];
__device__ float g_vw[2][8];
__device__ __align__(16) float g_ctxs[1024][8][64];   // 2 MB staging

__device__ __forceinline__ float ex2f(float x) {
    float r; asm("ex2.approx.ftz.f32 %0, %1;" : "=f"(r) : "f"(x)); return r;
}
__device__ __forceinline__ unsigned long long pack2(float a, float b) {
    unsigned long long r; asm("mov.b64 %0, {%1, %2};" : "=l"(r) : "f"(a), "f"(b)); return r;
}
__device__ __forceinline__ void unpack2(unsigned long long v, float& a, float& b) {
    asm("mov.b64 {%0, %1}, %2;" : "=f"(a), "=f"(b) : "l"(v));
}
__device__ __forceinline__ void fma2(unsigned long long& d, unsigned long long a, unsigned long long b) {
    asm("fma.rn.f32x2 %0, %1, %2, %0;" : "+l"(d) : "l"(a), "l"(b));
}
__device__ __forceinline__ float wsum(float v) {
#pragma unroll
    for (int m = 16; m > 0; m >>= 1) v += __shfl_xor_sync(0xffffffffu, v, m);
    return v;
}

// --- precompute: smem-staged kc/vc + bconst; block 0 also builds a[], vw -----
__global__ __launch_bounds__(256) void k_pre2(
        const float* __restrict__ fe_w,
        const float* __restrict__ fe_b, const float* __restrict__ pos_emb,
        const float* __restrict__ k_w, const float* __restrict__ k_b,
        const float* __restrict__ v_w, const float* __restrict__ v_b,
        const float* __restrict__ queries) {
    __shared__ float s_pos[8][64];         // pos_emb slice (8 s)
    __shared__ float s_kw[64][16];
    __shared__ float s_vw[64][16];
    __shared__ float s_feb[64];
    __shared__ float s_kc[8][16];
    __shared__ float s_part[2][8][16][2];  // [dh][s][j][{kc,vc}]
    __shared__ float s_kwf[16];

    const int t = threadIdx.x;
    const int s0 = blockIdx.x * 8;   // 128 blocks

    // ---- stage tables (float4 cooperative) ----
    if (t < 128) ((float4*)s_pos)[t] = ((const float4*)(pos_emb + s0 * 64))[t];
    ((float4*)s_kw)[t] = ((const float4*)k_w)[t];
    ((float4*)s_vw)[t] = ((const float4*)v_w)[t];
    if (t >= 128 && t < 144) ((float4*)s_feb)[t - 128] = ((const float4*)fe_b)[t - 128];
    __syncthreads();

    // ---- phase A: partial kc/vc over d-halves ----
    {
        const int j = t & 15, sl = (t >> 4) & 7, dh = t >> 7;
        float kc = 0.f, vc = 0.f;
#pragma unroll
        for (int u = 0; u < 32; u++) {
            int d = dh * 32 + u;
            float e = s_feb[d] + s_pos[sl][d];
            kc = fmaf(e, s_kw[d][j], kc);
            vc = fmaf(e, s_vw[d][j], vc);
        }
        s_part[dh][sl][j][0] = kc;
        s_part[dh][sl][j][1] = vc;
    }
    // block 0 only: kwf/vwf folds for a[] and vw
    if (blockIdx.x == 0 && t < 16) {
        float pk = 0.f, pv = 0.f;
        for (int d = 0; d < 64; d++) {
            float fw = __ldg(&fe_w[d]);
            pk = fmaf(fw, s_kw[d][t], pk);
            pv = fmaf(fw, s_vw[d][t], pv);
        }
        s_kwf[t] = pk;
        g_vw[t >> 3][t & 7] = pv;
    }
    __syncthreads();

    // ---- combine halves, write vc table ----
    if (t < 128) {
        const int sl = t >> 4, j = t & 15;
        const int s = s0 + sl;
        float kc = k_b[j] + s_part[0][sl][j][0] + s_part[1][sl][j][0];
        float vc = v_b[j] + s_part[0][sl][j][1] + s_part[1][sl][j][1];
        s_kc[sl][j] = kc;
        g_vc4[j >> 3][(j & 7) >> 1][s >> 1][(s & 1) * 2 + (j & 1)] = vc;
    }
    if (blockIdx.x == 0 && t >= 128 && t < 192) {
        int tt = t - 128;
        int g = tt >> 5, p = tt & 31, r = p >> 3, q = p & 7, h = g * 4 + r;
        float s = 0.f;
#pragma unroll
        for (int j = 0; j < 8; j++)
            s = fmaf(__ldg(&queries[q * 64 + h * 8 + j]), s_kwf[g * 8 + j], s);
        g_a[g][p] = s * LOG2E_OVER_SCALE;
    }
    __syncthreads();

    // ---- phase B: bconst (8 s x 64 pairs = 512 items, 2 per thread) ----
#pragma unroll
    for (int u = 0; u < 2; u++) {
        int item = t + 256 * u;
        int sl = item >> 6, pp = item & 63;
        int g = pp >> 5, p = pp & 31, r = p >> 3, q = p & 7, h = g * 4 + r;
        int s = s0 + sl;
        float acc = 0.f;
#pragma unroll
        for (int j = 0; j < 8; j++)
            acc = fmaf(__ldg(&queries[q * 64 + h * 8 + j]), s_kc[sl][g * 8 + j], acc);
        g_b4[g][p >> 1][s >> 1][(s & 1) * 2 + (p & 1)] = acc * LOG2E_OVER_SCALE;
    }
}

// --- main ---------------------------------------------------------------------
__global__ __launch_bounds__(512, 1) void k_main(const float* __restrict__ x,
                                                 float* __restrict__ attn_out) {
    extern __shared__ float smem[];
    float4* sm_vc = (float4*)smem;                  // [4][512] f4 = 32 KB
    float2* sm_x = (float2*)(smem + 8192);          // [2 buf][2 rows][512] f2 = 16 KB

    const int tid = threadIdx.x;
    const int w = tid >> 5, lane = tid & 31;
    const int g = blockIdx.y;
    const int p0 = 2 * w, p1 = p0 + 1;
    const float a0 = g_a[g][p0], a1 = g_a[g][p1];
    const int h0 = g * 4 + (p0 >> 3), q0 = p0 & 7;
    const int h1 = g * 4 + (p1 >> 3), q1 = p1 & 7;

    {
        const float4* vs = (const float4*)&g_vc4[g][0][0][0];
#pragma unroll
        for (int i = 0; i < 4; i++) sm_vc[tid + 512 * i] = vs[tid + 512 * i];
    }

    const int c0 = blockIdx.x;
    const float4* bptr = (const float4*)&g_b4[g][w][0][0];

    // ---- prologue: x + Z for first chunk ----
    ((float4*)sm_x)[tid] = ((const float4*)(x + (size_t)(2 * c0) * 1024))[tid];
    __syncthreads();
    float izA0, izA1, izB0, izB1;
    {
        float zA0 = 0.f, zA1 = 0.f, zB0 = 0.f, zB1 = 0.f;
#pragma unroll
        for (int i = 0; i < 16; i++) {
            int s2 = 32 * i + lane;
            float4 bb = __ldg(&bptr[s2]);
            float2 xA = sm_x[s2];
            float2 xB = sm_x[512 + s2];
            zA0 += ex2f(fmaf(a0, xA.x, bb.x)) + ex2f(fmaf(a0, xA.y, bb.z));
            zA1 += ex2f(fmaf(a1, xA.x, bb.y)) + ex2f(fmaf(a1, xA.y, bb.w));
            zB0 += ex2f(fmaf(a0, xB.x, bb.x)) + ex2f(fmaf(a0, xB.y, bb.z));
            zB1 += ex2f(fmaf(a1, xB.x, bb.y)) + ex2f(fmaf(a1, xB.y, bb.w));
        }
        izA0 = 1.0f / wsum(zA0); izA1 = 1.0f / wsum(zA1);
        izB0 = 1.0f / wsum(zB0); izB1 = 1.0f / wsum(zB1);
    }

    int cur = 0;
    for (int c = c0; c < 512; c += 74) {
        const int b0 = 2 * c, b1 = b0 + 1;
        const int cn = c + 74;
        if (cn < 512)
            ((float4*)&sm_x[(cur ^ 1) * 1024])[tid] =
                ((const float4*)(x + (size_t)(2 * cn) * 1024))[tid];
        __syncthreads();

        const float2* xc = &sm_x[cur * 1024];
        const float2* xn = &sm_x[(cur ^ 1) * 1024];
        float2* oA0 = (float2*)(attn_out + (((size_t)b0 * 8 + h0) * 8 + q0) * 1024) + lane;
        float2* oA1 = (float2*)(attn_out + (((size_t)b0 * 8 + h1) * 8 + q1) * 1024) + lane;
        float2* oB0 = (float2*)(attn_out + (((size_t)b1 * 8 + h0) * 8 + q0) * 1024) + lane;
        float2* oB1 = (float2*)(attn_out + (((size_t)b1 * 8 + h1) * 8 + q1) * 1024) + lane;

        float znA0 = 0.f, znA1 = 0.f, znB0 = 0.f, znB1 = 0.f;
        float xsA0 = 0.f, xsA1 = 0.f, xsB0 = 0.f, xsB1 = 0.f;
        unsigned long long cA0[4], cA1[4], cB0[4], cB1[4];
#pragma unroll
        for (int k = 0; k < 4; k++) { cA0[k] = cA1[k] = cB0[k] = cB1[k] = 0ull; }

        // 4-deep double-buffered bconst prefetch ring
        float4 bbA[4], bbB[4];
#pragma unroll
        for (int j = 0; j < 4; j++) bbA[j] = __ldg(&bptr[32 * j + lane]);

#pragma unroll
        for (int blk = 0; blk < 4; blk++) {
#pragma unroll
            for (int j = 0; j < 4; j++) {
                float4 nx;
                if (blk < 3) nx = __ldg(&bptr[32 * (4 * blk + 4 + j) + lane]);
                if (blk & 1) bbA[j] = nx; else bbB[j] = nx;
            }
#pragma unroll
            for (int j = 0; j < 4; j++) {
                const int i = 4 * blk + j;
                const int s2 = 32 * i + lane;
                const float4 bb = (blk & 1) ? bbB[j] : bbA[j];
                float2 xA = xc[s2];
                float2 xB = xc[512 + s2];
                float2 nA = xn[s2];
                float2 nB = xn[512 + s2];

                // Z pipeline for next chunk (reuses bb)
                znA0 += ex2f(fmaf(a0, nA.x, bb.x)) + ex2f(fmaf(a0, nA.y, bb.z));
                znA1 += ex2f(fmaf(a1, nA.x, bb.y)) + ex2f(fmaf(a1, nA.y, bb.w));
                znB0 += ex2f(fmaf(a0, nB.x, bb.x)) + ex2f(fmaf(a0, nB.y, bb.z));
                znB1 += ex2f(fmaf(a1, nB.x, bb.y)) + ex2f(fmaf(a1, nB.y, bb.w));

                float e00 = ex2f(fmaf(a0, xA.x, bb.x));
                float e01 = ex2f(fmaf(a0, xA.y, bb.z));
                float e10 = ex2f(fmaf(a1, xA.x, bb.y));
                float e11 = ex2f(fmaf(a1, xA.y, bb.w));
                float f00 = ex2f(fmaf(a0, xB.x, bb.x));
                float f01 = ex2f(fmaf(a0, xB.y, bb.z));
                float f10 = ex2f(fmaf(a1, xB.x, bb.y));
                float f11 = ex2f(fmaf(a1, xB.y, bb.w));

                xsA0 = fmaf(e00, xA.x, fmaf(e01, xA.y, xsA0));
                xsA1 = fmaf(e10, xA.x, fmaf(e11, xA.y, xsA1));
                xsB0 = fmaf(f00, xB.x, fmaf(f01, xB.y, xsB0));
                xsB1 = fmaf(f10, xB.x, fmaf(f11, xB.y, xsB1));

                unsigned long long pe00 = pack2(e00, e00), pe01 = pack2(e01, e01);
                unsigned long long pe10 = pack2(e10, e10), pe11 = pack2(e11, e11);
                unsigned long long pf00 = pack2(f00, f00), pf01 = pack2(f01, f01);
                unsigned long long pf10 = pack2(f10, f10), pf11 = pack2(f11, f11);
#pragma unroll
                for (int k = 0; k < 4; k++) {
                    float4 v4 = sm_vc[k * 512 + s2];
                    unsigned long long vlo = pack2(v4.x, v4.y);
                    unsigned long long vhi = pack2(v4.z, v4.w);
                    fma2(cA0[k], pe00, vlo); fma2(cA0[k], pe01, vhi);
                    fma2(cA1[k], pe10, vlo); fma2(cA1[k], pe11, vhi);
                    fma2(cB0[k], pf00, vlo); fma2(cB0[k], pf01, vhi);
                    fma2(cB1[k], pf10, vlo); fma2(cB1[k], pf11, vhi);
                }

                float2 r;
                r.x = e00 * izA0; r.y = e01 * izA0; __stcs(&oA0[i * 32], r);
                r.x = e10 * izA1; r.y = e11 * izA1; __stcs(&oA1[i * 32], r);
                r.x = f00 * izB0; r.y = f01 * izB0; __stcs(&oB0[i * 32], r);
                r.x = f10 * izB1; r.y = f11 * izB1; __stcs(&oB1[i * 32], r);
            }
        }

        // reductions
        znA0 = wsum(znA0); znA1 = wsum(znA1); znB0 = wsum(znB0); znB1 = wsum(znB1);
        xsA0 = wsum(xsA0); xsA1 = wsum(xsA1); xsB0 = wsum(xsB0); xsB1 = wsum(xsB1);
        float gA0[8], gA1[8], gB0[8], gB1[8];
#pragma unroll
        for (int k = 0; k < 4; k++) {
            unpack2(cA0[k], gA0[2 * k], gA0[2 * k + 1]);
            unpack2(cA1[k], gA1[2 * k], gA1[2 * k + 1]);
            unpack2(cB0[k], gB0[2 * k], gB0[2 * k + 1]);
            unpack2(cB1[k], gB1[2 * k], gB1[2 * k + 1]);
        }
#pragma unroll
        for (int j = 0; j < 8; j++) {
            gA0[j] = wsum(gA0[j]); gA1[j] = wsum(gA1[j]);
            gB0[j] = wsum(gB0[j]); gB1[j] = wsum(gB1[j]);
        }

        if (lane == 0) {
#pragma unroll
            for (int j = 0; j < 8; j++) {
                float vwj = g_vw[g][j];
                g_ctxs[b0][q0][h0 * 8 + j] = izA0 * fmaf(xsA0, vwj, gA0[j]);
                g_ctxs[b0][q1][h1 * 8 + j] = izA1 * fmaf(xsA1, vwj, gA1[j]);
                g_ctxs[b1][q0][h0 * 8 + j] = izB0 * fmaf(xsB0, vwj, gB0[j]);
                g_ctxs[b1][q1][h1 * 8 + j] = izB1 * fmaf(xsB1, vwj, gB1[j]);
            }
        }
        izA0 = 1.0f / znA0; izA1 = 1.0f / znA1;
        izB0 = 1.0f / znB0; izB1 = 1.0f / znB1;
        cur ^= 1;
    }
}

// --- out-projection: sync-free persistent GEMV -------------------------------
__global__ __launch_bounds__(1024) void k_outproj(const float* __restrict__ o_w,
                                                  const float* __restrict__ o_b,
                                                  float* __restrict__ out) {
    __shared__ float sw[4096];
    const int t = threadIdx.x;
    ((float4*)sw)[t] = ((const float4*)o_w)[t];
    __syncthreads();

    const int slot = t >> 9;         // 0/1: two b-rows in flight
    const int tt = t & 511;
    const int q = tt >> 6, e = tt & 63;
    const float bias = __ldg(&o_b[e]);

    for (int c = blockIdx.x; c < 512; c += 148) {
        const int b = 2 * c + slot;
        const float4* cr = (const float4*)&g_ctxs[b][q][0];
        float acc = bias;
#pragma unroll
        for (int k = 0; k < 16; k++) {
            float4 c4 = __ldg(&cr[k]);
            acc = fmaf(c4.x, sw[(4 * k + 0) * 64 + e], acc);
            acc = fmaf(c4.y, sw[(4 * k + 1) * 64 + e], acc);
            acc = fmaf(c4.z, sw[(4 * k + 2) * 64 + e], acc);
            acc = fmaf(c4.w, sw[(4 * k + 3) * 64 + e], acc);
        }
        out[(size_t)b * 512 + tt] = acc;
    }
}

// ---------------------------------------------------------------------------
extern "C" void kernel_launch(void* const* d_in, const int* in_sizes, int n_in,
                              void* d_out, int out_size) {
    const float* x       = (const float*)d_in[0];
    const float* queries = (const float*)d_in[1];
    const float* fe_w    = (const float*)d_in[2];
    const float* fe_b    = (const float*)d_in[3];
    const float* pos_emb = (const float*)d_in[4];
    const float* k_w     = (const float*)d_in[5];
    const float* k_b     = (const float*)d_in[6];
    const float* v_w     = (const float*)d_in[7];
    const float* v_b     = (const float*)d_in[8];
    const float* o_w     = (const float*)d_in[9];
    const float* o_b     = (const float*)d_in[10];

    float* out  = (float*)d_out;                 // [1024, 512]
    float* attn = out + 1024 * 512;              // [1024, 8, 8, 1024]

    int smem_bytes = (8192 + 8192) * 4;          // 65,536 B
    cudaFuncSetAttribute(k_main, cudaFuncAttributeMaxDynamicSharedMemorySize, smem_bytes);

    k_pre2<<<128, 256>>>(fe_w, fe_b, pos_emb, k_w, k_b, v_w, v_b, queries);
    k_main<<<dim3(74, 2), 512, smem_bytes>>>(x, attn);
    k_outproj<<<148, 1024>>>(o_w, o_b, out);
}

// round 7
// speedup vs baseline: 1.0507x; 1.0507x over previous
#include <cuda_runtime.h>

// ---------------------------------------------------------------------------
// GroupedQueryAttention:
//   x_embed affine in scalar x[b,s] => score(log2) = a[g,p]*x[b,s] + bconst[g,p,s]
//   attn = e/Z ; ctx = invZ*(sum_s e*vc[s,:] + (sum_s e*x)*vw) ; out = ctx@o_w+o_b
//
// k_main: grid (74,4) [g = y>>1, pair-half = y&1], 256 thr / 8 warps, 2 CTA/SM
// so barrier/reduction phases of one CTA overlap the other's inner loop.
// Warp w owns pairs (2wp, 2wp+1), wp = 8*(y&1)+w, over full s; NB=2 batch rows
// per chunk (each bconst LDG.128 / vc LDS.128 serves 8 elements). Z for the
// next chunk's rows is computed in the same inner loop (reuses the bconst
// load). attn stores are streaming (__stcs). No manual prefetch ring (R6
// post-mortem: it cost ~10us in register pressure / scheduling).
// ---------------------------------------------------------------------------

#define LOG2E_OVER_SCALE ((float)(1.4426950408889634 / 2.8284271247461903))

// g_b4[g][wp][s2][4] = { b(2s2,p0), b(2s2,p1), b(2s2+1,p0), b(2s2+1,p1) }
__device__ __align__(16) float g_b4[2][16][512][4];   // 256 KB
// g_vc4[g][jj][s2][4] = { vc(2s2,2jj), vc(2s2,2jj+1), vc(2s2+1,2jj), vc(2s2+1,2jj+1) }
__device__ __align__(16) float g_vc4[2][4][512][4];   // 64 KB
__device__ float g_a[2][32];
__device__ float g_vw[2][8];
__device__ __align__(16) float g_ctxs[1024][8][64];   // 2 MB staging

__device__ __forceinline__ float ex2f(float x) {
    float r; asm("ex2.approx.ftz.f32 %0, %1;" : "=f"(r) : "f"(x)); return r;
}
__device__ __forceinline__ unsigned long long pack2(float a, float b) {
    unsigned long long r; asm("mov.b64 %0, {%1, %2};" : "=l"(r) : "f"(a), "f"(b)); return r;
}
__device__ __forceinline__ void unpack2(unsigned long long v, float& a, float& b) {
    asm("mov.b64 {%0, %1}, %2;" : "=f"(a), "=f"(b) : "l"(v));
}
__device__ __forceinline__ void fma2(unsigned long long& d, unsigned long long a, unsigned long long b) {
    asm("fma.rn.f32x2 %0, %1, %2, %0;" : "+l"(d) : "l"(a), "l"(b));
}
__device__ __forceinline__ float wsum(float v) {
#pragma unroll
    for (int m = 16; m > 0; m >>= 1) v += __shfl_xor_sync(0xffffffffu, v, m);
    return v;
}

// --- precompute: smem-staged kc/vc + bconst; block 0 also builds a[], vw -----
__global__ __launch_bounds__(512) void k_pre2(
        const float* __restrict__ fe_w,
        const float* __restrict__ fe_b, const float* __restrict__ pos_emb,
        const float* __restrict__ k_w, const float* __restrict__ k_b,
        const float* __restrict__ v_w, const float* __restrict__ v_b,
        const float* __restrict__ queries) {
    __shared__ float s_pos[8][64];
    __shared__ float s_kw[64][16];
    __shared__ float s_vw[64][16];
    __shared__ float s_feb[64];
    __shared__ float s_kc[8][16];
    __shared__ float s_part[4][8][16][2];  // [dq][s][j][{kc,vc}]
    __shared__ float s_kwf[16];

    const int t = threadIdx.x;
    const int s0 = blockIdx.x * 8;   // 128 blocks

    // ---- stage tables (float4 cooperative) ----
    if (t < 128) {
        ((float4*)s_pos)[t] = ((const float4*)(pos_emb + s0 * 64))[t];
        ((float4*)s_vw)[128 + t] = ((const float4*)v_w)[128 + t];
    } else if (t < 384) {
        ((float4*)s_kw)[t - 128] = ((const float4*)k_w)[t - 128];
        if (t < 144) ((float4*)s_feb)[t - 128] = ((const float4*)fe_b)[t - 128];
    } else {
        ((float4*)s_vw)[t - 384] = ((const float4*)v_w)[t - 384];
    }
    __syncthreads();

    // ---- phase A: partial kc/vc over d-quarters ----
    {
        const int j = t & 15, sl = (t >> 4) & 7, dq = t >> 7;
        float kc = 0.f, vc = 0.f;
#pragma unroll
        for (int u = 0; u < 16; u++) {
            int d = dq * 16 + u;
            float e = s_feb[d] + s_pos[sl][d];
            kc = fmaf(e, s_kw[d][j], kc);
            vc = fmaf(e, s_vw[d][j], vc);
        }
        s_part[dq][sl][j][0] = kc;
        s_part[dq][sl][j][1] = vc;
    }
    if (blockIdx.x == 0 && t < 16) {
        float pk = 0.f, pv = 0.f;
        for (int d = 0; d < 64; d++) {
            float fw = __ldg(&fe_w[d]);
            pk = fmaf(fw, s_kw[d][t], pk);
            pv = fmaf(fw, s_vw[d][t], pv);
        }
        s_kwf[t] = pk;
        g_vw[t >> 3][t & 7] = pv;
    }
    __syncthreads();

    // ---- combine quarters, write vc table ----
    if (t < 128) {
        const int sl = t >> 4, j = t & 15;
        const int s = s0 + sl;
        float kc = k_b[j] + s_part[0][sl][j][0] + s_part[1][sl][j][0]
                          + s_part[2][sl][j][0] + s_part[3][sl][j][0];
        float vc = v_b[j] + s_part[0][sl][j][1] + s_part[1][sl][j][1]
                          + s_part[2][sl][j][1] + s_part[3][sl][j][1];
        s_kc[sl][j] = kc;
        g_vc4[j >> 3][(j & 7) >> 1][s >> 1][(s & 1) * 2 + (j & 1)] = vc;
    }
    if (blockIdx.x == 0 && t >= 128 && t < 192) {
        int tt = t - 128;
        int g = tt >> 5, p = tt & 31, r = p >> 3, q = p & 7, h = g * 4 + r;
        float s = 0.f;
#pragma unroll
        for (int j = 0; j < 8; j++)
            s = fmaf(__ldg(&queries[q * 64 + h * 8 + j]), s_kwf[g * 8 + j], s);
        g_a[g][p] = s * LOG2E_OVER_SCALE;
    }
    __syncthreads();

    // ---- phase B: bconst (8 s x 64 pairs = 512 items, 1 per thread) ----
    {
        int sl = t >> 6, pp = t & 63;
        int g = pp >> 5, p = pp & 31, r = p >> 3, q = p & 7, h = g * 4 + r;
        int s = s0 + sl;
        float acc = 0.f;
#pragma unroll
        for (int j = 0; j < 8; j++)
            acc = fmaf(__ldg(&queries[q * 64 + h * 8 + j]), s_kc[sl][g * 8 + j], acc);
        g_b4[g][p >> 1][s >> 1][(s & 1) * 2 + (p & 1)] = acc * LOG2E_OVER_SCALE;
    }
}

// --- main ---------------------------------------------------------------------
__global__ __launch_bounds__(256, 2) void k_main(const float* __restrict__ x,
                                                 float* __restrict__ attn_out) {
    extern __shared__ float smem[];
    float4* sm_vc = (float4*)smem;                  // [4][512] f4 = 32 KB
    float2* sm_x = (float2*)(smem + 8192);          // [2 buf][2 rows][512] f2 = 16 KB

    const int tid = threadIdx.x;
    const int w = tid >> 5, lane = tid & 31;
    const int g = blockIdx.y >> 1;
    const int wp = ((blockIdx.y & 1) << 3) + w;
    const int p0 = 2 * wp, p1 = p0 + 1;
    const float a0 = g_a[g][p0], a1 = g_a[g][p1];
    const int h0 = g * 4 + (p0 >> 3), q0 = p0 & 7;
    const int h1 = g * 4 + (p1 >> 3), q1 = p1 & 7;

    {
        const float4* vs = (const float4*)&g_vc4[g][0][0][0];
#pragma unroll
        for (int i = 0; i < 8; i++) sm_vc[tid + 256 * i] = vs[tid + 256 * i];
    }

    const int c0 = blockIdx.x;
    const float4* bptr = (const float4*)&g_b4[g][wp][0][0];

    // ---- prologue: x + Z for first chunk ----
    ((float4*)sm_x)[tid] = ((const float4*)(x + (size_t)(2 * c0) * 1024))[tid];
    ((float4*)sm_x)[tid + 256] = ((const float4*)(x + (size_t)(2 * c0) * 1024))[tid + 256];
    __syncthreads();
    float izA0, izA1, izB0, izB1;
    {
        float zA0 = 0.f, zA1 = 0.f, zB0 = 0.f, zB1 = 0.f;
#pragma unroll
        for (int i = 0; i < 16; i++) {
            int s2 = 32 * i + lane;
            float4 bb = bptr[s2];
            float2 xA = sm_x[s2];
            float2 xB = sm_x[512 + s2];
            zA0 += ex2f(fmaf(a0, xA.x, bb.x)) + ex2f(fmaf(a0, xA.y, bb.z));
            zA1 += ex2f(fmaf(a1, xA.x, bb.y)) + ex2f(fmaf(a1, xA.y, bb.w));
            zB0 += ex2f(fmaf(a0, xB.x, bb.x)) + ex2f(fmaf(a0, xB.y, bb.z));
            zB1 += ex2f(fmaf(a1, xB.x, bb.y)) + ex2f(fmaf(a1, xB.y, bb.w));
        }
        izA0 = 1.0f / wsum(zA0); izA1 = 1.0f / wsum(zA1);
        izB0 = 1.0f / wsum(zB0); izB1 = 1.0f / wsum(zB1);
    }

    int cur = 0;
    for (int c = c0; c < 512; c += 74) {
        const int b0 = 2 * c, b1 = b0 + 1;
        const int cn = c + 74;
        if (cn < 512) {
            ((float4*)&sm_x[(cur ^ 1) * 1024])[tid] =
                ((const float4*)(x + (size_t)(2 * cn) * 1024))[tid];
            ((float4*)&sm_x[(cur ^ 1) * 1024])[tid + 256] =
                ((const float4*)(x + (size_t)(2 * cn) * 1024))[tid + 256];
        }
        __syncthreads();

        const float2* xc = &sm_x[cur * 1024];
        const float2* xn = &sm_x[(cur ^ 1) * 1024];
        float2* oA0 = (float2*)(attn_out + (((size_t)b0 * 8 + h0) * 8 + q0) * 1024) + lane;
        float2* oA1 = (float2*)(attn_out + (((size_t)b0 * 8 + h1) * 8 + q1) * 1024) + lane;
        float2* oB0 = (float2*)(attn_out + (((size_t)b1 * 8 + h0) * 8 + q0) * 1024) + lane;
        float2* oB1 = (float2*)(attn_out + (((size_t)b1 * 8 + h1) * 8 + q1) * 1024) + lane;

        float znA0 = 0.f, znA1 = 0.f, znB0 = 0.f, znB1 = 0.f;
        float xsA0 = 0.f, xsA1 = 0.f, xsB0 = 0.f, xsB1 = 0.f;
        unsigned long long cA0[4], cA1[4], cB0[4], cB1[4];
#pragma unroll
        for (int k = 0; k < 4; k++) { cA0[k] = cA1[k] = cB0[k] = cB1[k] = 0ull; }

#pragma unroll
        for (int i = 0; i < 16; i++) {
            int s2 = 32 * i + lane;
            float4 bb = bptr[s2];
            float2 xA = xc[s2];
            float2 xB = xc[512 + s2];
            float2 nA = xn[s2];
            float2 nB = xn[512 + s2];

            // Z pipeline for next chunk (reuses bb)
            znA0 += ex2f(fmaf(a0, nA.x, bb.x)) + ex2f(fmaf(a0, nA.y, bb.z));
            znA1 += ex2f(fmaf(a1, nA.x, bb.y)) + ex2f(fmaf(a1, nA.y, bb.w));
            znB0 += ex2f(fmaf(a0, nB.x, bb.x)) + ex2f(fmaf(a0, nB.y, bb.z));
            znB1 += ex2f(fmaf(a1, nB.x, bb.y)) + ex2f(fmaf(a1, nB.y, bb.w));

            float e00 = ex2f(fmaf(a0, xA.x, bb.x));
            float e01 = ex2f(fmaf(a0, xA.y, bb.z));
            float e10 = ex2f(fmaf(a1, xA.x, bb.y));
            float e11 = ex2f(fmaf(a1, xA.y, bb.w));
            float f00 = ex2f(fmaf(a0, xB.x, bb.x));
            float f01 = ex2f(fmaf(a0, xB.y, bb.z));
            float f10 = ex2f(fmaf(a1, xB.x, bb.y));
            float f11 = ex2f(fmaf(a1, xB.y, bb.w));

            xsA0 = fmaf(e00, xA.x, fmaf(e01, xA.y, xsA0));
            xsA1 = fmaf(e10, xA.x, fmaf(e11, xA.y, xsA1));
            xsB0 = fmaf(f00, xB.x, fmaf(f01, xB.y, xsB0));
            xsB1 = fmaf(f10, xB.x, fmaf(f11, xB.y, xsB1));

            unsigned long long pe00 = pack2(e00, e00), pe01 = pack2(e01, e01);
            unsigned long long pe10 = pack2(e10, e10), pe11 = pack2(e11, e11);
            unsigned long long pf00 = pack2(f00, f00), pf01 = pack2(f01, f01);
            unsigned long long pf10 = pack2(f10, f10), pf11 = pack2(f11, f11);
#pragma unroll
            for (int k = 0; k < 4; k++) {
                float4 v4 = sm_vc[k * 512 + s2];
                unsigned long long vlo = pack2(v4.x, v4.y);
                unsigned long long vhi = pack2(v4.z, v4.w);
                fma2(cA0[k], pe00, vlo); fma2(cA0[k], pe01, vhi);
                fma2(cA1[k], pe10, vlo); fma2(cA1[k], pe11, vhi);
                fma2(cB0[k], pf00, vlo); fma2(cB0[k], pf01, vhi);
                fma2(cB1[k], pf10, vlo); fma2(cB1[k], pf11, vhi);
            }

            float2 r;
            r.x = e00 * izA0; r.y = e01 * izA0; __stcs(&oA0[i * 32], r);
            r.x = e10 * izA1; r.y = e11 * izA1; __stcs(&oA1[i * 32], r);
            r.x = f00 * izB0; r.y = f01 * izB0; __stcs(&oB0[i * 32], r);
            r.x = f10 * izB1; r.y = f11 * izB1; __stcs(&oB1[i * 32], r);
        }

        // reductions
        znA0 = wsum(znA0); znA1 = wsum(znA1); znB0 = wsum(znB0); znB1 = wsum(znB1);
        xsA0 = wsum(xsA0); xsA1 = wsum(xsA1); xsB0 = wsum(xsB0); xsB1 = wsum(xsB1);
        float gA0[8], gA1[8], gB0[8], gB1[8];
#pragma unroll
        for (int k = 0; k < 4; k++) {
            unpack2(cA0[k], gA0[2 * k], gA0[2 * k + 1]);
            unpack2(cA1[k], gA1[2 * k], gA1[2 * k + 1]);
            unpack2(cB0[k], gB0[2 * k], gB0[2 * k + 1]);
            unpack2(cB1[k], gB1[2 * k], gB1[2 * k + 1]);
        }
#pragma unroll
        for (int j = 0; j < 8; j++) {
            gA0[j] = wsum(gA0[j]); gA1[j] = wsum(gA1[j]);
            gB0[j] = wsum(gB0[j]); gB1[j] = wsum(gB1[j]);
        }

        if (lane == 0) {
#pragma unroll
            for (int j = 0; j < 8; j++) {
                float vwj = g_vw[g][j];
                g_ctxs[b0][q0][h0 * 8 + j] = izA0 * fmaf(xsA0, vwj, gA0[j]);
                g_ctxs[b0][q1][h1 * 8 + j] = izA1 * fmaf(xsA1, vwj, gA1[j]);
                g_ctxs[b1][q0][h0 * 8 + j] = izB0 * fmaf(xsB0, vwj, gB0[j]);
                g_ctxs[b1][q1][h1 * 8 + j] = izB1 * fmaf(xsB1, vwj, gB1[j]);
            }
        }
        izA0 = 1.0f / znA0; izA1 = 1.0f / znA1;
        izB0 = 1.0f / znB0; izB1 = 1.0f / znB1;
        cur ^= 1;
    }
}

// --- out-projection: sync-free persistent GEMV -------------------------------
__global__ __launch_bounds__(1024) void k_outproj(const float* __restrict__ o_w,
                                                  const float* __restrict__ o_b,
                                                  float* __restrict__ out) {
    __shared__ float sw[4096];
    const int t = threadIdx.x;
    ((float4*)sw)[t] = ((const float4*)o_w)[t];
    __syncthreads();

    const int slot = t >> 9;         // 0/1: two b-rows in flight
    const int tt = t & 511;
    const int q = tt >> 6, e = tt & 63;
    const float bias = __ldg(&o_b[e]);

    for (int c = blockIdx.x; c < 512; c += 148) {
        const int b = 2 * c + slot;
        const float4* cr = (const float4*)&g_ctxs[b][q][0];
        float acc = bias;
#pragma unroll
        for (int k = 0; k < 16; k++) {
            float4 c4 = __ldg(&cr[k]);
            acc = fmaf(c4.x, sw[(4 * k + 0) * 64 + e], acc);
            acc = fmaf(c4.y, sw[(4 * k + 1) * 64 + e], acc);
            acc = fmaf(c4.z, sw[(4 * k + 2) * 64 + e], acc);
            acc = fmaf(c4.w, sw[(4 * k + 3) * 64 + e], acc);
        }
        out[(size_t)b * 512 + tt] = acc;
    }
}

// ---------------------------------------------------------------------------
extern "C" void kernel_launch(void* const* d_in, const int* in_sizes, int n_in,
                              void* d_out, int out_size) {
    const float* x       = (const float*)d_in[0];
    const float* queries = (const float*)d_in[1];
    const float* fe_w    = (const float*)d_in[2];
    const float* fe_b    = (const float*)d_in[3];
    const float* pos_emb = (const float*)d_in[4];
    const float* k_w     = (const float*)d_in[5];
    const float* k_b     = (const float*)d_in[6];
    const float* v_w     = (const float*)d_in[7];
    const float* v_b     = (const float*)d_in[8];
    const float* o_w     = (const float*)d_in[9];
    const float* o_b     = (const float*)d_in[10];

    float* out  = (float*)d_out;                 // [1024, 512]
    float* attn = out + 1024 * 512;              // [1024, 8, 8, 1024]

    int smem_bytes = (8192 + 4096) * 4;          // 49,152 B per CTA
    cudaFuncSetAttribute(k_main, cudaFuncAttributeMaxDynamicSharedMemorySize, smem_bytes);

    k_pre2<<<128, 512>>>(fe_w, fe_b, pos_emb, k_w, k_b, v_w, v_b, queries);
    k_main<<<dim3(74, 4), 256, smem_bytes>>>(x, attn);
    k_outproj<<<148, 1024>>>(o_w, o_b, out);
}